// round 9
// baseline (speedup 1.0000x reference)
#include <cuda_runtime.h>
#include <math.h>

#define BB 2
#define HH 1024
#define WW 1024
#define NPIX (HH*WW)
#define KK 16
#define NBINS 4096
#define PER_T (NBINS/1024)
#define CHUNKS 16
#define CHUNK_PIX (NPIX/CHUNKS)

// ---------------- scratch (static device globals: no allocation) ----------------
__device__ double g_acc[BB*KK*8];      // 0 cnt,1 sx,2 sy,3 ccnt,4 csx,5 csy,6 ssig0,7 ssig1
__device__ double g_seedbg[BB];
__device__ double g_var[BB*KK];
__device__ double g_sfg[BB*KK];
__device__ float  g_lov[BB*KK];
__device__ float  g_params[BB*KK*8];   // 0 cx,1 cy,2 sx,3 sy,4 present,5 sm0,6 sm1,7 gts(count)
__device__ unsigned int g_hist[BB*KK*2*NBINS];
__device__ unsigned int g_cen_nonzero;
__device__ float g_ex[BB*NPIX];
__device__ float g_ey[BB*NPIX];
__device__ float g_seed[BB*NPIX];

// ---------------- kernel 0: zero all accumulators ----------------
__global__ void zero_kernel() {
    int idx = blockIdx.x * blockDim.x + threadIdx.x;
    int stride = gridDim.x * blockDim.x;
    for (int i = idx; i < BB*KK*2*NBINS; i += stride) g_hist[i] = 0u;
    if (idx < BB*KK*8) g_acc[idx] = 0.0;
    if (idx < BB*KK) { g_var[idx] = 0.0; g_sfg[idx] = 0.0; g_lov[idx] = 0.f; }
    if (idx < BB) g_seedbg[idx] = 0.0;
    if (idx == 0) g_cen_nonzero = 0u;
}

// ---------------- kernel 1: detect center_images dtype (bool u8 vs int32) ------
// Read first BB*NPIX BYTES (safe under both layouts). For int32 {0,1} values,
// bytes at offsets i%4 != 0 are all zero; for packed bool they are ~50% ones.
__global__ void detect_kernel(const unsigned char* __restrict__ cen) {
    unsigned int local = 0;
    int stride = gridDim.x * blockDim.x;
    for (int i = blockIdx.x*blockDim.x + threadIdx.x; i < BB*NPIX; i += stride) {
        if ((i & 3) && cen[i]) local++;
    }
    #pragma unroll
    for (int o = 16; o; o >>= 1) local += __shfl_down_sync(0xffffffffu, local, o);
    if ((threadIdx.x & 31) == 0 && local) atomicAdd(&g_cen_nonzero, local);
}

// ---------------- kernel 2: per-pixel pass 1 (stats + precompute) -------------
__global__ void __launch_bounds__(256) pass1_kernel(
    const float* __restrict__ pred, const float* __restrict__ xym,
    const int* __restrict__ inst, const int* __restrict__ lab,
    const unsigned char* __restrict__ cen)
{
    __shared__ float sacc[KK*8];
    __shared__ float sbg;
    int b = blockIdx.y;
    for (int t = threadIdx.x; t < KK*8; t += 256) sacc[t] = 0.f;
    if (threadIdx.x == 0) sbg = 0.f;
    __syncthreads();

    bool cen_i32 = (g_cen_nonzero == 0u);
    const int* cen_i = (const int*)cen;
    const float* pb = pred + (size_t)b * 5 * NPIX;
    size_t boff = (size_t)b * NPIX;
    float bg_local = 0.f;
    int start = blockIdx.x * 4096;

    #pragma unroll 4
    for (int r = 0; r < 16; r++) {
        int i = start + r*256 + threadIdx.x;
        float xm = xym[i];
        float ym = xym[NPIX + i];
        float a0 = pb[i];
        float a1 = pb[NPIX + i];
        float a4 = pb[4*NPIX + i];
        float ex = tanhf(a0) + xm;
        float ey = tanhf(a1) + ym;
        float sd = 1.f / (1.f + __expf(-a4));
        g_ex[boff + i] = ex;
        g_ey[boff + i] = ey;
        g_seed[boff + i] = sd;

        int iv = inst[boff + i];
        if (iv >= 1 && iv <= KK) {
            float a2 = pb[2*NPIX + i];
            float a3 = pb[3*NPIX + i];
            float* s = &sacc[(iv-1)*8];
            atomicAdd(s+0, 1.f);
            atomicAdd(s+1, xm);
            atomicAdd(s+2, ym);
            atomicAdd(s+6, a2);
            atomicAdd(s+7, a3);
            bool c = cen_i32 ? (cen_i[boff + i] != 0) : (cen[boff + i] != 0);
            if (c) {
                atomicAdd(s+3, 1.f);
                atomicAdd(s+4, xm);
                atomicAdd(s+5, ym);
            }
        }
        if (lab[boff + i] == 0) bg_local += sd * sd;
    }
    #pragma unroll
    for (int o = 16; o; o >>= 1) bg_local += __shfl_down_sync(0xffffffffu, bg_local, o);
    if ((threadIdx.x & 31) == 0) atomicAdd(&sbg, bg_local);
    __syncthreads();

    for (int t = threadIdx.x; t < KK*8; t += 256) {
        float v = sacc[t];
        if (v != 0.f) atomicAdd(&g_acc[b*KK*8 + t], (double)v);
    }
    if (threadIdx.x == 0) atomicAdd(&g_seedbg[b], (double)sbg);
}

// ---------------- kernel 3: per-instance params ----------------
__global__ void param_kernel() {
    int t = blockIdx.x * blockDim.x + threadIdx.x;
    if (t >= BB*KK) return;
    const double* a = &g_acc[t*8];
    double count = a[0];
    float present = count > 0.0 ? 1.f : 0.f;
    double cnt = count > 0.0 ? count : 1.0;
    double cx, cy;
    if (a[3] == 1.0) { cx = a[4]; cy = a[5]; }       // exactly one center pixel
    else             { cx = a[1] / cnt; cy = a[2] / cnt; }
    float sm0 = (float)(a[6] / cnt);
    float sm1 = (float)(a[7] / cnt);
    float* p = &g_params[t*8];
    p[0] = (float)cx; p[1] = (float)cy;
    p[2] = expf(10.f * sm0); p[3] = expf(10.f * sm1);
    p[4] = present; p[5] = sm0; p[6] = sm1; p[7] = (float)count;
}

// ---------------- kernel 4: dist + error histogram + var/seed_fg -------------
__global__ void __launch_bounds__(512) hist_kernel(
    const float* __restrict__ pred, const int* __restrict__ inst)
{
    __shared__ unsigned int sh[2*NBINS];   // [neg | pos] counts, 32 KB
    __shared__ float red_var[16], red_sfg[16];
    int b = blockIdx.z, k = blockIdx.y, chunk = blockIdx.x;
    const float* p = &g_params[(b*KK + k)*8];
    float present = p[4];
    for (int t = threadIdx.x; t < 2*NBINS; t += 512) sh[t] = 0u;
    __syncthreads();
    if (present == 0.f) return;   // uniform over block

    float cx = p[0], cy = p[1], sxv = p[2], syv = p[3], sm0 = p[5], sm1 = p[6];
    size_t boff = (size_t)b * NPIX;
    const float* pr2 = pred + ((size_t)b*5 + 2) * NPIX;
    const float* pr3 = pred + ((size_t)b*5 + 3) * NPIX;
    int target = k + 1;
    int start = chunk * CHUNK_PIX;
    float var_l = 0.f, sfg_l = 0.f;

    for (int i = start + threadIdx.x; i < start + CHUNK_PIX; i += 512) {
        float ex = g_ex[boff + i];
        float ey = g_ey[boff + i];
        int iv = inst[boff + i];
        float dx = ex - cx, dy = ey - cy;
        float dist = __expf(-(dx*dx*sxv + dy*dy*syv));
        bool pos = (iv == target);
        float e = pos ? (2.f - 2.f*dist) : (2.f*dist);
        int bin = (int)(e * (float)(NBINS/2));
        bin = min(max(bin, 0), NBINS - 1);
        atomicAdd(&sh[(pos ? NBINS : 0) + bin], 1u);
        if (pos) {
            float d0 = pr2[i] - sm0;
            float d1 = pr3[i] - sm1;
            var_l += d0*d0 + d1*d1;
            float ds = g_seed[boff + i] - dist;
            sfg_l += ds*ds;
        }
    }
    #pragma unroll
    for (int o = 16; o; o >>= 1) {
        var_l += __shfl_down_sync(0xffffffffu, var_l, o);
        sfg_l += __shfl_down_sync(0xffffffffu, sfg_l, o);
    }
    int warp = threadIdx.x >> 5, lane = threadIdx.x & 31;
    if (lane == 0) { red_var[warp] = var_l; red_sfg[warp] = sfg_l; }
    __syncthreads();
    if (threadIdx.x == 0) {
        float v = 0.f, s = 0.f;
        for (int w = 0; w < 16; w++) { v += red_var[w]; s += red_sfg[w]; }
        atomicAdd(&g_var[b*KK + k], (double)v);
        atomicAdd(&g_sfg[b*KK + k], (double)s);
    }
    unsigned int* gh = &g_hist[(size_t)(b*KK + k)*2*NBINS];
    for (int t = threadIdx.x; t < 2*NBINS; t += 512) {
        unsigned int v = sh[t];
        if (v) atomicAdd(&gh[t], v);
    }
}

// ---------------- kernel 5: Lovász hinge via descending histogram scan -------
__global__ void __launch_bounds__(1024) lovasz_kernel() {
    int k = blockIdx.x, b = blockIdx.y;
    const float* p = &g_params[(b*KK + k)*8];
    float present = p[4];
    float gtsf = p[7];
    if (present == 0.f) { if (threadIdx.x == 0) g_lov[b*KK + k] = 0.f; return; }

    const unsigned int* hneg = &g_hist[(size_t)(b*KK + k)*2*NBINS];
    const unsigned int* hpos = hneg + NBINS;
    int t = threadIdx.x;
    int lane = t & 31, warp = t >> 5;

    unsigned int np[PER_T], nn[PER_T];
    unsigned int csum = 0, psum = 0;
    #pragma unroll
    for (int r = 0; r < PER_T; r++) {
        int bin = NBINS - 1 - (t*PER_T + r);  // descending error order
        np[r] = hpos[bin]; nn[r] = hneg[bin];
        csum += np[r] + nn[r]; psum += np[r];
    }
    // block exclusive scan of (count, pos) packed in u64
    unsigned long long v = ((unsigned long long)psum << 32) | (unsigned long long)csum;
    unsigned long long inc = v;
    #pragma unroll
    for (int o = 1; o < 32; o <<= 1) {
        unsigned long long u = __shfl_up_sync(0xffffffffu, inc, o);
        if (lane >= o) inc += u;
    }
    __shared__ unsigned long long wsum[32];
    if (lane == 31) wsum[warp] = inc;
    __syncthreads();
    if (warp == 0) {
        unsigned long long w = wsum[lane];
        #pragma unroll
        for (int o = 1; o < 32; o <<= 1) {
            unsigned long long u = __shfl_up_sync(0xffffffffu, w, o);
            if (lane >= o) w += u;
        }
        wsum[lane] = w;
    }
    __syncthreads();
    unsigned long long ex = inc - v + (warp > 0 ? wsum[warp-1] : 0ULL);

    double i  = (double)(unsigned int)(ex & 0xffffffffULL);
    double P  = (double)(unsigned int)(ex >> 32);
    double gts = (double)gtsf;
    double jb = 1.0 - (gts - P) / (gts + i - P);   // jacc before this thread's bins
    double contrib = 0.0;
    #pragma unroll
    for (int r = 0; r < PER_T; r++) {
        unsigned int c = np[r] + nn[r];
        if (c) {
            int bin = NBINS - 1 - (t*PER_T + r);
            i += (double)c; P += (double)np[r];
            double ja = 1.0 - (gts - P) / (gts + i - P);
            double e = ((double)bin + 0.5) * (2.0 / NBINS);  // bin midpoint error
            contrib += e * (ja - jb);
            jb = ja;
        }
    }
    #pragma unroll
    for (int o = 16; o; o >>= 1) contrib += __shfl_down_sync(0xffffffffu, contrib, o);
    __shared__ double cred[32];
    if (lane == 0) cred[warp] = contrib;
    __syncthreads();
    if (t == 0) {
        double s = 0.0;
        for (int w = 0; w < 32; w++) s += cred[w];
        g_lov[b*KK + k] = (float)s;
    }
}

// ---------------- kernel 6: final combine ----------------
__global__ void final_kernel(float* out) {
    double total = 0.0;
    for (int b = 0; b < BB; b++) {
        double sum_pres = 0.0, inst_s = 0.0, var_s = 0.0, sfg_s = 0.0;
        for (int k = 0; k < KK; k++) {
            const float* p = &g_params[(b*KK + k)*8];
            double pres = (double)p[4];
            double cnt = p[7] > 0.f ? (double)p[7] : 1.0;
            sum_pres += pres;
            inst_s += (double)g_lov[b*KK + k] * pres;
            var_s  += (g_var[b*KK + k] / (2.0 * cnt)) * pres;  // N_SIGMA = 2
            sfg_s  += g_sfg[b*KK + k] * pres;                  // FG_W = 1
        }
        double obj = sum_pres > 1.0 ? sum_pres : 1.0;
        double seed_loss = (g_seedbg[b] + sfg_s) / (double)(HH * WW);
        total += (inst_s / obj) + 10.0 * (var_s / obj) + seed_loss;  // W_INST=1,W_VAR=10,W_SEED=1
    }
    *out = (float)(total / BB);
}

// ---------------- launch ----------------
extern "C" void kernel_launch(void* const* d_in, const int* in_sizes, int n_in,
                              void* d_out, int out_size)
{
    const float* pred = (const float*)d_in[0];
    const float* xym  = (const float*)d_in[1];
    const int*   inst = (const int*)d_in[2];
    const int*   lab  = (const int*)d_in[3];
    const unsigned char* cen = (const unsigned char*)d_in[4];
    float* out = (float*)d_out;

    zero_kernel<<<512, 256>>>();
    detect_kernel<<<128, 256>>>(cen);
    pass1_kernel<<<dim3(NPIX/4096, BB), 256>>>(pred, xym, inst, lab, cen);
    param_kernel<<<1, 32>>>();
    hist_kernel<<<dim3(CHUNKS, KK, BB), 512>>>(pred, inst);
    lovasz_kernel<<<dim3(KK, BB), 1024>>>();
    final_kernel<<<1, 1>>>(out);
}